// round 12
// baseline (speedup 1.0000x reference)
#include <cuda_runtime.h>

typedef unsigned long long ull;

#define N_QUBITS 10
#define N_LAYERS 3
#define BATCH    16384
#define PI_F     3.14159265358979f

#define THREADS        224
#define WARPS_PER_BLK  7
#define NPACK (N_LAYERS * N_QUBITS * 7)   // 210 packed ulls

// Per-(layer,qubit) fused unitary U = Rz*Ry*Rx (SU(2)), 7 broadcast f32x2 packs:
// q=0..8: [0]=c00r [1]=c00i [2]=-c00i [3]=c01r [4]=-c01r [5]=c01i [6]=-c01i
// q=9 (packed-bit half-swap form):
//         [0]=C1r [1]=C1i [2]=-C1i [3]=C2r [4]=C2i [5]=-C2i [6]=0
//         where C1=(u00,u11) lo/hi, C2=(u01,u10) lo/hi.
__device__ ull g_P[NPACK];

// ---------------- f32x2 helpers ----------------
__device__ __forceinline__ ull pk(float lo, float hi) {
    ull r; asm("mov.b64 %0, {%1, %2};" : "=l"(r) : "f"(lo), "f"(hi)); return r;
}
__device__ __forceinline__ float getlo(ull v) {
    float a, b; asm("mov.b64 {%0, %1}, %2;" : "=f"(a), "=f"(b) : "l"(v)); return a;
}
__device__ __forceinline__ float gethi(ull v) {
    float a, b; asm("mov.b64 {%0, %1}, %2;" : "=f"(a), "=f"(b) : "l"(v)); return b;
}
__device__ __forceinline__ ull swap2(ull v) {
    float a, b; asm("mov.b64 {%0, %1}, %2;" : "=f"(a), "=f"(b) : "l"(v));
    ull r; asm("mov.b64 %0, {%1, %2};" : "=l"(r) : "f"(b), "f"(a)); return r;
}
__device__ __forceinline__ ull fma2(ull a, ull b, ull c) {
    ull r; asm("fma.rn.f32x2 %0, %1, %2, %3;" : "=l"(r) : "l"(a), "l"(b), "l"(c)); return r;
}
__device__ __forceinline__ ull mul2(ull a, ull b) {
    ull r; asm("mul.rn.f32x2 %0, %1, %2;" : "=l"(r) : "l"(a), "l"(b)); return r;
}
__device__ __forceinline__ ull add2(ull a, ull b) {
    ull r; asm("add.rn.f32x2 %0, %1, %2;" : "=l"(r) : "l"(a), "l"(b)); return r;
}

__global__ void prep_kernel(const float* __restrict__ w) {
    int i = threadIdx.x;          // 0..29 -> (layer, qubit)
    if (i >= N_LAYERS * N_QUBITS) return;
    float a = w[i * 3 + 0] * 0.5f;
    float b = w[i * 3 + 1] * 0.5f;
    float g = w[i * 3 + 2] * 0.5f;
    float ca, sa, cb, sb, cg, sg;
    sincosf(a, &sa, &ca);
    sincosf(b, &sb, &cb);
    sincosf(g, &sg, &cg);
    // M = Ry * Rx
    float m00r = cb * ca, m00i =  sb * sa;
    float m01r = -sb * ca, m01i = -cb * sa;
    float m10r =  sb * ca, m10i = -cb * sa;
    float m11r =  cb * ca, m11i = -sb * sa;
    // row0 *= (cg - i sg), row1 *= (cg + i sg)
    float u00r = cg * m00r + sg * m00i, u00i = cg * m00i - sg * m00r;
    float u01r = cg * m01r + sg * m01i, u01i = cg * m01i - sg * m01r;
    float u10r = cg * m10r - sg * m10i, u10i = cg * m10i + sg * m10r;
    float u11r = cg * m11r - sg * m11i, u11i = cg * m11i + sg * m11r;
    ull* P = g_P + i * 7;
    if ((i % N_QUBITS) == 9) {
        // half-swap packs: C1=(u00,u11), C2=(u01,u10)
        P[0] = pk(u00r, u11r);   P[1] = pk(u00i, u11i);   P[2] = pk(-u00i, -u11i);
        P[3] = pk(u01r, u10r);   P[4] = pk(u01i, u10i);   P[5] = pk(-u01i, -u10i);
        P[6] = 0ull;
    } else {
        P[0] = pk(u00r, u00r);   P[1] = pk(u00i, u00i);   P[2] = pk(-u00i, -u00i);
        P[3] = pk(u01r, u01r);   P[4] = pk(-u01r, -u01r);
        P[5] = pk(u01i, u01i);   P[6] = pk(-u01i, -u01i);
    }
}

// ---------------- gates on packed state (16 x f32x2 per component) ----------
// amplitude index k (10 bits): bit0 = packed half, bits 1..4 = packed reg p,
// bits 5..9 = lane.  qubit q <-> k-bit (9-q).

template<int LB>
__device__ __forceinline__ void gate_cross(ull reP[16], ull imP[16],
                                           const ull* Pg, int lane) {
    const bool hi = (lane & (1 << LB)) != 0;
    ull c00r = Pg[0], c00i = Pg[1], n00i = Pg[2];
    ull c01r = Pg[3], n01r = Pg[4], c01i = Pg[5], n01i = Pg[6];
    // mine = hi ? u11=conj(u00) : u00 ; partner = hi ? u10=-conj(u01) : u01
    ull mr  = c00r;
    ull mi  = hi ? n00i : c00i;
    ull nmi = hi ? c00i : n00i;
    ull pr  = hi ? n01r : c01r;
    ull pi  = c01i;
    ull npi = n01i;
#pragma unroll
    for (int p = 0; p < 16; p++) {
        ull xr = __shfl_xor_sync(0xffffffffu, reP[p], 1 << LB);
        ull xi = __shfl_xor_sync(0xffffffffu, imP[p], 1 << LB);
        ull r = reP[p], i = imP[p];
        ull t = mul2(mr, r); t = fma2(nmi, i, t);
        t = fma2(pr, xr, t); t = fma2(npi, xi, t);
        ull u = mul2(mi, r); u = fma2(mr, i, u);
        u = fma2(pi, xr, u); u = fma2(pr, xi, u);
        reP[p] = t; imP[p] = u;
    }
}

template<int PB>
__device__ __forceinline__ void gate_local(ull reP[16], ull imP[16],
                                           const ull* Pg) {
    ull c00r = Pg[0], c00i = Pg[1], n00i = Pg[2];
    ull c01r = Pg[3], n01r = Pg[4], c01i = Pg[5], n01i = Pg[6];
#pragma unroll
    for (int p = 0; p < 16; p++) {
        if (p & (1 << PB)) continue;
        const int p1 = p | (1 << PB);
        ull ar = reP[p], ai = imP[p], br = reP[p1], bi = imP[p1];
        ull t;
        // row0 = u00*a + u01*b
        t = mul2(c00r, ar); t = fma2(n00i, ai, t); t = fma2(c01r, br, t); t = fma2(n01i, bi, t); reP[p]  = t;
        t = mul2(c00i, ar); t = fma2(c00r, ai, t); t = fma2(c01i, br, t); t = fma2(c01r, bi, t); imP[p]  = t;
        // row1 = u10*a + u11*b,  u10=(-c01r,c01i), u11=(c00r,-c00i)
        t = mul2(n01r, ar); t = fma2(n01i, ai, t); t = fma2(c00r, br, t); t = fma2(c00i, bi, t); reP[p1] = t;
        t = mul2(c01i, ar); t = fma2(n01r, ai, t); t = fma2(n00i, br, t); t = fma2(c00r, bi, t); imP[p1] = t;
    }
}

// Gate on k-bit 0 (qubit 9): half-swap f32x2 form.
__device__ __forceinline__ void gate_bit0(ull reP[16], ull imP[16],
                                          const ull* Pg) {
    ull C1r = Pg[0], C1i = Pg[1], nC1i = Pg[2];
    ull C2r = Pg[3], C2i = Pg[4], nC2i = Pg[5];
#pragma unroll
    for (int p = 0; p < 16; p++) {
        ull vr = reP[p], vi = imP[p];
        ull sr = swap2(vr), si = swap2(vi);
        ull t = mul2(C1r, vr); t = fma2(nC1i, vi, t);
        t = fma2(C2r, sr, t);  t = fma2(nC2i, si, t);
        ull u = mul2(C1i, vr); u = fma2(C1r, vi, u);
        u = fma2(C2i, sr, u);  u = fma2(C2r, si, u);
        reP[p] = t; imP[p] = u;
    }
}

// Fused CNOT-ring permutation of one state component via per-warp smem buffer.
// Target (lane', p', half'): source reg = Gray(p')^(lane'_0?8:0), half = p'&1
// (hi-target half flipped), source lane = srcE (even j') / srcO (odd j').
__device__ __forceinline__ void perm_comp(ull P[16], char* wb, int lane,
                                          unsigned eOff, unsigned oOff,
                                          unsigned rx8) {
#pragma unroll
    for (int p = 0; p < 16; p++)
        *(ull*)(wb + p * 256 + lane * 8) = P[p];
    __syncwarp();
#pragma unroll
    for (int p = 0; p < 16; p++) {
        const int g = p ^ (p >> 1);                 // Gray(p)
        unsigned ro = ((unsigned)(g << 8)) ^ rx8;   // reg byte offset (^2048)
        float lo = *(const float*)(wb + eOff + ro + ((p & 1) << 2));
        float hi = *(const float*)(wb + oOff + ro + (((p & 1) ^ 1) << 2));
        P[p] = pk(lo, hi);
    }
    __syncwarp();
}

__global__ void __launch_bounds__(THREADS, 3)
vql_kernel(const float* __restrict__ x, float* __restrict__ out) {
    __shared__ ull sP[NPACK];
    __shared__ ull sBuf[WARPS_PER_BLK][16][32];
    for (int t = threadIdx.x; t < NPACK; t += THREADS) sP[t] = g_P[t];
    __syncthreads();

    const int warp_id = blockIdx.x * WARPS_PER_BLK + (threadIdx.x >> 5);
    const int lane = threadIdx.x & 31;
    if (warp_id >= BATCH) return;
    const int b = warp_id;
    char* wb = (char*)sBuf[threadIdx.x >> 5];

    // ---- encoding angles ----
    float xin = 0.0f;
    if (lane < N_QUBITS) xin = x[b * N_QUBITS + lane];
    float h = tanhf(xin) * (0.5f * PI_F);
    float cl, sl;
    sincosf(h, &sl, &cl);
    float cq[N_QUBITS], sq[N_QUBITS];
#pragma unroll
    for (int q = 0; q < N_QUBITS; q++) {
        cq[q] = __shfl_sync(0xffffffffu, cl, q);
        sq[q] = __shfl_sync(0xffffffffu, sl, q);
    }

    // ---- init product state (real) ----
    float lf = 1.0f;
#pragma unroll
    for (int lb = 0; lb < 5; lb++)
        lf *= ((lane >> lb) & 1) ? sq[4 - lb] : cq[4 - lb];

    float bp[16];
    bp[0] = lf;
#pragma unroll
    for (int pb = 0; pb < 4; pb++) {          // p-bit pb <-> qubit 8-pb
#pragma unroll
        for (int t = 0; t < (1 << pb); t++) {
            float v = bp[t];
            bp[t]              = v * cq[8 - pb];
            bp[t | (1 << pb)]  = v * sq[8 - pb];
        }
    }
    ull reP[16], imP[16];
#pragma unroll
    for (int p = 0; p < 16; p++) {
        reP[p] = pk(bp[p] * cq[9], bp[p] * sq[9]);   // half <-> qubit 9
        imP[p] = 0ull;
    }

    // permutation gather constants
    const int srcE = lane ^ (lane >> 1);
    const int srcO = srcE ^ 24;
    const unsigned eOff = (unsigned)(srcE * 8);
    const unsigned oOff = (unsigned)(srcO * 8);
    const unsigned rx8  = (lane & 1) ? 2048u : 0u;   // reg-index ^8 in bytes

    // ---- layers ----
#pragma unroll 1
    for (int layer = 0; layer < N_LAYERS; layer++) {
        const ull* PL = sP + layer * N_QUBITS * 7;

        // fused CNOT ring (one linear-GF(2) index permutation)
        perm_comp(reP, wb, lane, eOff, oOff, rx8);
        if (layer != 0)                      // layer 0: im identically zero
            perm_comp(imP, wb, lane, eOff, oOff, rx8);

        // gates q = 0..9
        gate_cross<4>(reP, imP, PL + 0 * 7, lane);   // q=0 (k bit 9)
        gate_cross<3>(reP, imP, PL + 1 * 7, lane);   // q=1
        gate_cross<2>(reP, imP, PL + 2 * 7, lane);   // q=2
        gate_cross<1>(reP, imP, PL + 3 * 7, lane);   // q=3
        gate_cross<0>(reP, imP, PL + 4 * 7, lane);   // q=4 (k bit 5)
        gate_local<3>(reP, imP, PL + 5 * 7);         // q=5 (k bit 4)
        gate_local<2>(reP, imP, PL + 6 * 7);         // q=6
        gate_local<1>(reP, imP, PL + 7 * 7);         // q=7
        gate_local<0>(reP, imP, PL + 8 * 7);         // q=8 (k bit 1)
        gate_bit0(reP, imP, PL + 9 * 7);             // q=9 (k bit 0)
    }

    // ---- measurement ----
    ull Sa = 0ull, A1 = 0ull, A2 = 0ull, A3 = 0ull, A4 = 0ull;
#pragma unroll
    for (int p = 0; p < 16; p++) {
        ull pp = mul2(reP[p], reP[p]);
        pp = fma2(imP[p], imP[p], pp);
        Sa = add2(Sa, pp);
        if (p & 1) A1 = add2(A1, pp);
        if (p & 2) A2 = add2(A2, pp);
        if (p & 4) A3 = add2(A3, pp);
        if (p & 8) A4 = add2(A4, pp);
    }
    float S  = getlo(Sa) + gethi(Sa);
    float S0 = gethi(Sa);                       // k bit0 set
    float S1 = getlo(A1) + gethi(A1);
    float S2 = getlo(A2) + gethi(A2);
    float S3 = getlo(A3) + gethi(A3);
    float S4 = getlo(A4) + gethi(A4);

    // v[0..4] + total via one signed Walsh-Hadamard butterfly of S:
    // final lane m holds sum_l (-1)^{popc(l&m)} S(l); lane 2^s -> w = 4-s.
    float u = S;
#pragma unroll
    for (int s = 0; s < 5; s++) {
        float t = __shfl_xor_sync(0xffffffffu, u, 1 << s);
        u = (lane & (1 << s)) ? (t - u) : (t + u);
    }

    // v[5..9]: plain sums of per-lane scalars, packed f32x2 reductions
    ull z0 = pk(S - 2.0f * S4, S - 2.0f * S3);
    ull z1 = pk(S - 2.0f * S2, S - 2.0f * S1);
    ull z2 = pk(S - 2.0f * S0, 0.0f);
#pragma unroll
    for (int off = 16; off > 0; off >>= 1) {
        z0 = add2(z0, __shfl_xor_sync(0xffffffffu, z0, off));
        z1 = add2(z1, __shfl_xor_sync(0xffffffffu, z1, off));
        z2 = add2(z2, __shfl_xor_sync(0xffffffffu, z2, off));
    }

    if (lane == 0) {
        out[b * N_QUBITS + 5] = getlo(z0);
        out[b * N_QUBITS + 6] = gethi(z0);
        out[b * N_QUBITS + 7] = getlo(z1);
        out[b * N_QUBITS + 8] = gethi(z1);
        out[b * N_QUBITS + 9] = getlo(z2);
    } else if (!(lane & (lane - 1))) {          // lane is a power of two
        int s = __ffs(lane) - 1;                // lane = 1<<s
        out[b * N_QUBITS + (4 - s)] = u;
    }
}

extern "C" void kernel_launch(void* const* d_in, const int* in_sizes, int n_in,
                              void* d_out, int out_size) {
    const float* x = (const float*)d_in[0];        // (16384, 10)
    const float* w = (const float*)d_in[1];        // (3, 10, 3)
    float* out = (float*)d_out;                    // (16384, 10)
    prep_kernel<<<1, 32>>>(w);
    const int blocks = (BATCH + WARPS_PER_BLK - 1) / WARPS_PER_BLK;  // 2341
    vql_kernel<<<blocks, THREADS>>>(x, out);
}

// round 14
// speedup vs baseline: 1.2692x; 1.2692x over previous
#include <cuda_runtime.h>

typedef unsigned long long ull;

#define N_QUBITS 10
#define N_LAYERS 3
#define BATCH    16384
#define PI_F     3.14159265358979f

#define THREADS        256
#define WARPS_PER_BLK  8
#define NPACK (N_LAYERS * N_QUBITS * 7)   // 210 packed ulls

// Per-(layer,qubit) fused unitary U = Rz*Ry*Rx (SU(2)), 7 broadcast f32x2 packs:
// q=0..8: [0]=c00r [1]=c00i [2]=-c00i [3]=c01r [4]=-c01r [5]=c01i [6]=-c01i
// q=9 (packed-bit half-swap form):
//         [0]=C1r [1]=C1i [2]=-C1i [3]=C2r [4]=C2i [5]=-C2i [6]=0
//         where C1=(u00,u11) lo/hi, C2=(u01,u10) lo/hi.
__device__ ull g_P[NPACK];

// ---------------- f32x2 helpers ----------------
__device__ __forceinline__ ull pk(float lo, float hi) {
    ull r; asm("mov.b64 %0, {%1, %2};" : "=l"(r) : "f"(lo), "f"(hi)); return r;
}
__device__ __forceinline__ float getlo(ull v) {
    float a, b; asm("mov.b64 {%0, %1}, %2;" : "=f"(a), "=f"(b) : "l"(v)); return a;
}
__device__ __forceinline__ float gethi(ull v) {
    float a, b; asm("mov.b64 {%0, %1}, %2;" : "=f"(a), "=f"(b) : "l"(v)); return b;
}
__device__ __forceinline__ ull swap2(ull v) {
    float a, b; asm("mov.b64 {%0, %1}, %2;" : "=f"(a), "=f"(b) : "l"(v));
    ull r; asm("mov.b64 %0, {%1, %2};" : "=l"(r) : "f"(b), "f"(a)); return r;
}
__device__ __forceinline__ ull fma2(ull a, ull b, ull c) {
    ull r; asm("fma.rn.f32x2 %0, %1, %2, %3;" : "=l"(r) : "l"(a), "l"(b), "l"(c)); return r;
}
__device__ __forceinline__ ull mul2(ull a, ull b) {
    ull r; asm("mul.rn.f32x2 %0, %1, %2;" : "=l"(r) : "l"(a), "l"(b)); return r;
}
__device__ __forceinline__ ull add2(ull a, ull b) {
    ull r; asm("add.rn.f32x2 %0, %1, %2;" : "=l"(r) : "l"(a), "l"(b)); return r;
}

__global__ void prep_kernel(const float* __restrict__ w) {
    int i = threadIdx.x;          // 0..29 -> (layer, qubit)
    if (i >= N_LAYERS * N_QUBITS) return;
    float a = w[i * 3 + 0] * 0.5f;
    float b = w[i * 3 + 1] * 0.5f;
    float g = w[i * 3 + 2] * 0.5f;
    float ca, sa, cb, sb, cg, sg;
    sincosf(a, &sa, &ca);
    sincosf(b, &sb, &cb);
    sincosf(g, &sg, &cg);
    // M = Ry * Rx
    float m00r = cb * ca, m00i =  sb * sa;
    float m01r = -sb * ca, m01i = -cb * sa;
    float m10r =  sb * ca, m10i = -cb * sa;
    float m11r =  cb * ca, m11i = -sb * sa;
    // row0 *= (cg - i sg), row1 *= (cg + i sg)
    float u00r = cg * m00r + sg * m00i, u00i = cg * m00i - sg * m00r;
    float u01r = cg * m01r + sg * m01i, u01i = cg * m01i - sg * m01r;
    float u10r = cg * m10r - sg * m10i, u10i = cg * m10i + sg * m10r;
    float u11r = cg * m11r - sg * m11i, u11i = cg * m11i + sg * m11r;
    ull* P = g_P + i * 7;
    if ((i % N_QUBITS) == 9) {
        // half-swap packs: C1=(u00,u11), C2=(u01,u10)
        P[0] = pk(u00r, u11r);   P[1] = pk(u00i, u11i);   P[2] = pk(-u00i, -u11i);
        P[3] = pk(u01r, u10r);   P[4] = pk(u01i, u10i);   P[5] = pk(-u01i, -u10i);
        P[6] = 0ull;
    } else {
        P[0] = pk(u00r, u00r);   P[1] = pk(u00i, u00i);   P[2] = pk(-u00i, -u00i);
        P[3] = pk(u01r, u01r);   P[4] = pk(-u01r, -u01r);
        P[5] = pk(u01i, u01i);   P[6] = pk(-u01i, -u01i);
    }
}

// ---------------- gates on packed state (16 x f32x2 per component) ----------
// amplitude index k (10 bits): bit0 = packed half, bits 1..4 = packed reg p,
// bits 5..9 = lane.  qubit q <-> k-bit (9-q).

template<int LB>
__device__ __forceinline__ void gate_cross(ull reP[16], ull imP[16],
                                           const ull* Pg, int lane) {
    const bool hi = (lane & (1 << LB)) != 0;
    ull c00r = Pg[0], c00i = Pg[1], n00i = Pg[2];
    ull c01r = Pg[3], n01r = Pg[4], c01i = Pg[5], n01i = Pg[6];
    // mine = hi ? u11=conj(u00) : u00 ; partner = hi ? u10=-conj(u01) : u01
    ull mr  = c00r;
    ull mi  = hi ? n00i : c00i;
    ull nmi = hi ? c00i : n00i;
    ull pr  = hi ? n01r : c01r;
    ull pi  = c01i;
    ull npi = n01i;
#pragma unroll
    for (int p = 0; p < 16; p++) {
        ull xr = __shfl_xor_sync(0xffffffffu, reP[p], 1 << LB);
        ull xi = __shfl_xor_sync(0xffffffffu, imP[p], 1 << LB);
        ull r = reP[p], i = imP[p];
        ull t = mul2(mr, r); t = fma2(nmi, i, t);
        t = fma2(pr, xr, t); t = fma2(npi, xi, t);
        ull u = mul2(mi, r); u = fma2(mr, i, u);
        u = fma2(pi, xr, u); u = fma2(pr, xi, u);
        reP[p] = t; imP[p] = u;
    }
}

template<int PB>
__device__ __forceinline__ void gate_local(ull reP[16], ull imP[16],
                                           const ull* Pg) {
    ull c00r = Pg[0], c00i = Pg[1], n00i = Pg[2];
    ull c01r = Pg[3], n01r = Pg[4], c01i = Pg[5], n01i = Pg[6];
#pragma unroll
    for (int p = 0; p < 16; p++) {
        if (p & (1 << PB)) continue;
        const int p1 = p | (1 << PB);
        ull ar = reP[p], ai = imP[p], br = reP[p1], bi = imP[p1];
        ull t;
        // row0 = u00*a + u01*b
        t = mul2(c00r, ar); t = fma2(n00i, ai, t); t = fma2(c01r, br, t); t = fma2(n01i, bi, t); reP[p]  = t;
        t = mul2(c00i, ar); t = fma2(c00r, ai, t); t = fma2(c01i, br, t); t = fma2(c01r, bi, t); imP[p]  = t;
        // row1 = u10*a + u11*b,  u10=(-c01r,c01i), u11=(c00r,-c00i)
        t = mul2(n01r, ar); t = fma2(n01i, ai, t); t = fma2(c00r, br, t); t = fma2(c00i, bi, t); reP[p1] = t;
        t = mul2(c01i, ar); t = fma2(n01r, ai, t); t = fma2(n00i, br, t); t = fma2(c00r, bi, t); imP[p1] = t;
    }
}

// Gate on k-bit 0 (qubit 9): half-swap f32x2 form.
__device__ __forceinline__ void gate_bit0(ull reP[16], ull imP[16],
                                          const ull* Pg) {
    ull C1r = Pg[0], C1i = Pg[1], nC1i = Pg[2];
    ull C2r = Pg[3], C2i = Pg[4], nC2i = Pg[5];
#pragma unroll
    for (int p = 0; p < 16; p++) {
        ull vr = reP[p], vi = imP[p];
        ull sr = swap2(vr), si = swap2(vi);
        ull t = mul2(C1r, vr); t = fma2(nC1i, vi, t);
        t = fma2(C2r, sr, t);  t = fma2(nC2i, si, t);
        ull u = mul2(C1i, vr); u = fma2(C1r, vi, u);
        u = fma2(C2i, sr, u);  u = fma2(C2r, si, u);
        reP[p] = t; imP[p] = u;
    }
}

// Fused CNOT-ring permutation of one state component via per-warp smem buffer.
// Target (lane', p', half'): source reg = Gray(p')^(lane'_0?8:0), half = p'&1
// (hi-target half flipped), source lane = srcE (even j') / srcO (odd j').
__device__ __forceinline__ void perm_comp(ull P[16], char* wb, int lane,
                                          unsigned eOff, unsigned oOff,
                                          unsigned rx8) {
#pragma unroll
    for (int p = 0; p < 16; p++)
        *(ull*)(wb + p * 256 + lane * 8) = P[p];
    __syncwarp();
#pragma unroll
    for (int p = 0; p < 16; p++) {
        const int g = p ^ (p >> 1);                 // Gray(p)
        unsigned ro = ((unsigned)(g << 8)) ^ rx8;   // reg byte offset (^2048)
        float lo = *(const float*)(wb + eOff + ro + ((p & 1) << 2));
        float hi = *(const float*)(wb + oOff + ro + (((p & 1) ^ 1) << 2));
        P[p] = pk(lo, hi);
    }
    __syncwarp();
}

__global__ void __launch_bounds__(THREADS, 2)
vql_kernel(const float* __restrict__ x, float* __restrict__ out) {
    __shared__ ull sP[NPACK];
    __shared__ ull sBuf[WARPS_PER_BLK][16][32];
    for (int t = threadIdx.x; t < NPACK; t += THREADS) sP[t] = g_P[t];
    __syncthreads();

    const int warp_id = blockIdx.x * WARPS_PER_BLK + (threadIdx.x >> 5);
    const int lane = threadIdx.x & 31;
    if (warp_id >= BATCH) return;
    const int b = warp_id;
    char* wb = (char*)sBuf[threadIdx.x >> 5];

    // ---- encoding angles ----
    float xin = 0.0f;
    if (lane < N_QUBITS) xin = x[b * N_QUBITS + lane];
    float h = tanhf(xin) * (0.5f * PI_F);
    float cl, sl;
    sincosf(h, &sl, &cl);
    float cq[N_QUBITS], sq[N_QUBITS];
#pragma unroll
    for (int q = 0; q < N_QUBITS; q++) {
        cq[q] = __shfl_sync(0xffffffffu, cl, q);
        sq[q] = __shfl_sync(0xffffffffu, sl, q);
    }

    // ---- init product state (real) ----
    float lf = 1.0f;
#pragma unroll
    for (int lb = 0; lb < 5; lb++)
        lf *= ((lane >> lb) & 1) ? sq[4 - lb] : cq[4 - lb];

    float bp[16];
    bp[0] = lf;
#pragma unroll
    for (int pb = 0; pb < 4; pb++) {          // p-bit pb <-> qubit 8-pb
#pragma unroll
        for (int t = 0; t < (1 << pb); t++) {
            float v = bp[t];
            bp[t]              = v * cq[8 - pb];
            bp[t | (1 << pb)]  = v * sq[8 - pb];
        }
    }
    ull reP[16], imP[16];
#pragma unroll
    for (int p = 0; p < 16; p++) {
        reP[p] = pk(bp[p] * cq[9], bp[p] * sq[9]);   // half <-> qubit 9
        imP[p] = 0ull;
    }

    // permutation gather constants
    const int srcE = lane ^ (lane >> 1);
    const int srcO = srcE ^ 24;
    const unsigned eOff = (unsigned)(srcE * 8);
    const unsigned oOff = (unsigned)(srcO * 8);
    const unsigned rx8  = (lane & 1) ? 2048u : 0u;   // reg-index ^8 in bytes

    // ---- layers ----
#pragma unroll 1
    for (int layer = 0; layer < N_LAYERS; layer++) {
        const ull* PL = sP + layer * N_QUBITS * 7;

        // fused CNOT ring (one linear-GF(2) index permutation)
        perm_comp(reP, wb, lane, eOff, oOff, rx8);
        if (layer != 0)                      // layer 0: im identically zero
            perm_comp(imP, wb, lane, eOff, oOff, rx8);

        // gates q = 0..9
        gate_cross<4>(reP, imP, PL + 0 * 7, lane);   // q=0 (k bit 9)
        gate_cross<3>(reP, imP, PL + 1 * 7, lane);   // q=1
        gate_cross<2>(reP, imP, PL + 2 * 7, lane);   // q=2
        gate_cross<1>(reP, imP, PL + 3 * 7, lane);   // q=3
        gate_cross<0>(reP, imP, PL + 4 * 7, lane);   // q=4 (k bit 5)
        gate_local<3>(reP, imP, PL + 5 * 7);         // q=5 (k bit 4)
        gate_local<2>(reP, imP, PL + 6 * 7);         // q=6
        gate_local<1>(reP, imP, PL + 7 * 7);         // q=7
        gate_local<0>(reP, imP, PL + 8 * 7);         // q=8 (k bit 1)
        gate_bit0(reP, imP, PL + 9 * 7);             // q=9 (k bit 0)
    }

    // ---- measurement ----
    ull Sa = 0ull, A1 = 0ull, A2 = 0ull, A3 = 0ull, A4 = 0ull;
#pragma unroll
    for (int p = 0; p < 16; p++) {
        ull pp = mul2(reP[p], reP[p]);
        pp = fma2(imP[p], imP[p], pp);
        Sa = add2(Sa, pp);
        if (p & 1) A1 = add2(A1, pp);
        if (p & 2) A2 = add2(A2, pp);
        if (p & 4) A3 = add2(A3, pp);
        if (p & 8) A4 = add2(A4, pp);
    }
    float S  = getlo(Sa) + gethi(Sa);
    float S0 = gethi(Sa);                       // k bit0 set
    float S1 = getlo(A1) + gethi(A1);
    float S2 = getlo(A2) + gethi(A2);
    float S3 = getlo(A3) + gethi(A3);
    float S4 = getlo(A4) + gethi(A4);

    // v[0..4] + total via one signed Walsh-Hadamard butterfly of S:
    // final lane m holds sum_l (-1)^{popc(l&m)} S(l); lane 2^s -> w = 4-s.
    float u = S;
#pragma unroll
    for (int s = 0; s < 5; s++) {
        float t = __shfl_xor_sync(0xffffffffu, u, 1 << s);
        u = (lane & (1 << s)) ? (t - u) : (t + u);
    }

    // v[5..9]: plain sums of per-lane scalars, packed f32x2 reductions
    ull z0 = pk(S - 2.0f * S4, S - 2.0f * S3);
    ull z1 = pk(S - 2.0f * S2, S - 2.0f * S1);
    ull z2 = pk(S - 2.0f * S0, 0.0f);
#pragma unroll
    for (int off = 16; off > 0; off >>= 1) {
        z0 = add2(z0, __shfl_xor_sync(0xffffffffu, z0, off));
        z1 = add2(z1, __shfl_xor_sync(0xffffffffu, z1, off));
        z2 = add2(z2, __shfl_xor_sync(0xffffffffu, z2, off));
    }

    if (lane == 0) {
        out[b * N_QUBITS + 5] = getlo(z0);
        out[b * N_QUBITS + 6] = gethi(z0);
        out[b * N_QUBITS + 7] = getlo(z1);
        out[b * N_QUBITS + 8] = gethi(z1);
        out[b * N_QUBITS + 9] = getlo(z2);
    } else if (!(lane & (lane - 1))) {          // lane is a power of two
        int s = __ffs(lane) - 1;                // lane = 1<<s
        out[b * N_QUBITS + (4 - s)] = u;
    }
}

extern "C" void kernel_launch(void* const* d_in, const int* in_sizes, int n_in,
                              void* d_out, int out_size) {
    const float* x = (const float*)d_in[0];        // (16384, 10)
    const float* w = (const float*)d_in[1];        // (3, 10, 3)
    float* out = (float*)d_out;                    // (16384, 10)
    prep_kernel<<<1, 32>>>(w);
    const int blocks = BATCH / WARPS_PER_BLK;      // 2048
    vql_kernel<<<blocks, THREADS>>>(x, out);
}